// round 6
// baseline (speedup 1.0000x reference)
#include <cuda_runtime.h>
#include <cuda_bf16.h>
#include <math.h>

#define NN 200000
#define EE 6400000
#define GG 2000
#define ROW 16      // floats per state row (64B)
#define SBS 512
#define NB1 ((NN + SBS - 1) / SBS)   // 391 scan blocks

__device__ __align__(256) float  g_S0[NN * ROW];
__device__ __align__(256) float  g_S1[NN * ROW];
__device__ __align__(16)  float4 g_c4[NN];
__device__ __align__(256) float  g_gs[GG * ROW];
__device__ __align__(32)  float4 g_rec[(size_t)EE * 2];  // 32B record per edge: {geo4 | from,to,pad,pad}
__device__ int g_cnt[NN];
__device__ int g_off[NN];
__device__ int g_part[SBS];

__device__ __forceinline__ float tanh_acc(float x) {
    float ax = fabsf(x);
    float e;
    asm("ex2.approx.f32 %0, %1;" : "=f"(e) : "f"(ax * -2.8853900817779268f));
    float r;
    asm("rcp.approx.f32 %0, %1;" : "=f"(r) : "f"(1.0f + e));
    return copysignf((1.0f - e) * r, x);
}
__device__ __forceinline__ float softplus_acc(float x) {
    return log1pf(expf(-fabsf(x))) + fmaxf(x, 0.0f);
}
__device__ __forceinline__ void ld_v8(const float* p, float* s) {
    asm("ld.global.nc.v8.f32 {%0,%1,%2,%3,%4,%5,%6,%7}, [%8];"
        : "=f"(s[0]), "=f"(s[1]), "=f"(s[2]), "=f"(s[3]),
          "=f"(s[4]), "=f"(s[5]), "=f"(s[6]), "=f"(s[7])
        : "l"(p));
}
__device__ __forceinline__ void st_v8(float* p, const float* s) {
    asm volatile("st.global.v8.f32 [%0], {%1,%2,%3,%4,%5,%6,%7,%8};"
                 :: "l"(p), "f"(s[0]), "f"(s[1]), "f"(s[2]), "f"(s[3]),
                    "f"(s[4]), "f"(s[5]), "f"(s[6]), "f"(s[7]) : "memory");
}
__device__ __forceinline__ void red_v4(float* p, float a, float b, float c, float d) {
    asm volatile("red.global.add.v4.f32 [%0], {%1,%2,%3,%4};"
                 :: "l"(p), "f"(a), "f"(b), "f"(c), "f"(d) : "memory");
}
__device__ __forceinline__ void red_v2(float* p, float a, float b) {
    asm volatile("red.global.add.v2.f32 [%0], {%1,%2};"
                 :: "l"(p), "f"(a), "f"(b) : "memory");
}
__device__ __forceinline__ void red_row(float* dst, const float* a) {
    red_v4(dst,     a[0], a[1], a[2], a[3]);
    red_v4(dst + 4, a[4], a[5], a[6], a[7]);
    red_v2(dst + 8, a[8], a[9]);
}

__global__ void init_kernel(const float* __restrict__ coords) {
    int i = blockIdx.x * blockDim.x + threadIdx.x;
    if (i < NN * ROW) g_S1[i] = 0.f;
    if (i < NN)       g_c4[i] = make_float4(coords[3*i], coords[3*i+1], coords[3*i+2], 0.f);
    if (i < NN)       g_cnt[i] = 0;
    if (i < GG * ROW) g_gs[i] = 0.f;
}

__global__ void hist_kernel(const int* __restrict__ nt) {
    int e = blockIdx.x * blockDim.x + threadIdx.x;
    if (e < EE) atomicAdd(&g_cnt[nt[e]], 1);
}

__global__ void scan1_kernel() {
    __shared__ int s[SBS];
    int tid = threadIdx.x;
    int gid = blockIdx.x * SBS + tid;
    int v = (gid < NN) ? g_cnt[gid] : 0;
    s[tid] = v;
    __syncthreads();
#pragma unroll
    for (int d = 1; d < SBS; d <<= 1) {
        int t = (tid >= d) ? s[tid - d] : 0;
        __syncthreads();
        s[tid] += t;
        __syncthreads();
    }
    if (gid < NN) g_off[gid] = s[tid] - v;          // exclusive
    if (tid == SBS - 1) g_part[blockIdx.x] = s[SBS - 1];
}

__global__ void scan2_kernel() {
    __shared__ int s[SBS];
    int tid = threadIdx.x;
    int v = (tid < NB1) ? g_part[tid] : 0;
    s[tid] = v;
    __syncthreads();
#pragma unroll
    for (int d = 1; d < SBS; d <<= 1) {
        int t = (tid >= d) ? s[tid - d] : 0;
        __syncthreads();
        s[tid] += t;
        __syncthreads();
    }
    if (tid < NB1) g_part[tid] = s[tid] - v;        // exclusive over block totals
}

__global__ void scan3_kernel() {
    int gid = blockIdx.x * SBS + threadIdx.x;
    if (gid < NN) g_off[gid] += g_part[blockIdx.x];
}

// Compute geo per edge, allocate to-sorted slot, write 32B record {geo, from, to}.
__global__ void scatter_kernel(const int* __restrict__ nf, const int* __restrict__ nt,
                               const float* __restrict__ el, const float* __restrict__ ev) {
    int e = blockIdx.x * blockDim.x + threadIdx.x;
    if (e >= EE) return;
    int from = nf[e];
    int to   = nt[e];
    float4 cf = g_c4[from];
    float4 ct = g_c4[to];
    float e0 = ev[3*e], e1 = ev[3*e+1], e2 = ev[3*e+2];

    float r[8];
    r[0] = el[e];
    r[1] = fabsf(cf.x) + fabsf(cf.y) + fabsf(cf.z);
    r[2] = cf.x*ct.x + cf.y*ct.y + cf.z*ct.z;
    r[3] = cf.x*e0 + cf.y*e1 + cf.z*e2;
    r[4] = __int_as_float(from);
    r[5] = __int_as_float(to);
    r[6] = 0.f; r[7] = 0.f;

    int pos = atomicAdd(&g_off[to], 1);
    st_v8((float*)(g_rec + 2*(size_t)pos), r);
}

// Round 0: state == 0; records sorted by `to` => reds near-coalesced.
__global__ void round0_kernel(const float* __restrict__ Wm, const float* __restrict__ bm,
                              float* __restrict__ Sout) {
    __shared__ float sW[140];
    __shared__ float sB[10];
    int tid = threadIdx.x;
    if (tid < 140) sW[tid] = Wm[tid];
    if (tid < 10)  sB[tid] = bm[tid];
    __syncthreads();

    int e = blockIdx.x * blockDim.x + tid;
    if (e >= EE) return;

    float r[8];
    ld_v8((const float*)(g_rec + 2*(size_t)e), r);
    int to = __float_as_int(r[5]);

    float acc[10];
#pragma unroll
    for (int j = 0; j < 10; j++)
        acc[j] = tanh_acc(sB[j] + r[0]*sW[100+j] + r[1]*sW[110+j] + r[2]*sW[120+j] + r[3]*sW[130+j]);

    red_row(Sout + (size_t)to * ROW, acc);
}

// Rounds 1..2: coalesced record + random state gather + near-coalesced reds.
__global__ void round_kernel(const float* __restrict__ Wm, const float* __restrict__ bm,
                             const float* __restrict__ Sin, float* __restrict__ Sout) {
    __shared__ float sW[140];
    __shared__ float sB[10];
    int tid = threadIdx.x;
    if (tid < 140) sW[tid] = Wm[tid];
    if (tid < 10)  sB[tid] = bm[tid];
    __syncthreads();

    int e = blockIdx.x * blockDim.x + tid;
    if (e >= EE) return;

    float r[8];
    ld_v8((const float*)(g_rec + 2*(size_t)e), r);
    int from = __float_as_int(r[4]);
    int to   = __float_as_int(r[5]);

    const float* srow = Sin + (size_t)from * ROW;
    float s[10];
    ld_v8(srow, s);
    asm("ld.global.nc.v2.f32 {%0,%1}, [%2];" : "=f"(s[8]), "=f"(s[9]) : "l"(srow + 8));

    float acc[10];
#pragma unroll
    for (int j = 0; j < 10; j++)
        acc[j] = sB[j] + r[0]*sW[100+j] + r[1]*sW[110+j] + r[2]*sW[120+j] + r[3]*sW[130+j];
#pragma unroll
    for (int i = 0; i < 10; i++) {
#pragma unroll
        for (int j = 0; j < 10; j++) acc[j] += s[i] * sW[i*10+j];
    }
#pragma unroll
    for (int j = 0; j < 10; j++) acc[j] = tanh_acc(acc[j]);

    red_row(Sout + (size_t)to * ROW, acc);
}

__global__ void copy_kernel(const float4* __restrict__ src, float4* __restrict__ dst) {
    int i = blockIdx.x * blockDim.x + threadIdx.x;
    if (i < NN * 4) dst[i] = src[i];
}

__global__ void node_kernel(const int* __restrict__ ngi, const float* __restrict__ S) {
    int i = blockIdx.x * blockDim.x + threadIdx.x;
    if (i >= NN) return;
    int g = ngi[i];
    const float* srow = S + (size_t)i * ROW;
    float s[10];
    ld_v8(srow, s);
    asm("ld.global.nc.v2.f32 {%0,%1}, [%2];" : "=f"(s[8]), "=f"(s[9]) : "l"(srow + 8));
    red_row(g_gs + (size_t)g * ROW, s);
}

__global__ void out_kernel(const float* __restrict__ Wo, const float* __restrict__ bo,
                           float* __restrict__ out) {
    int g = blockIdx.x * blockDim.x + threadIdx.x;
    if (g >= GG) return;
    float ev[4];
#pragma unroll
    for (int k = 0; k < 4; k++) ev[k] = bo[k];
#pragma unroll
    for (int j = 0; j < 10; j++) {
        float s = g_gs[g * ROW + j];
#pragma unroll
        for (int k = 0; k < 4; k++) ev[k] += s * Wo[j*4+k];
    }
    out[4*g+0] = ev[0];
    out[4*g+1] = softplus_acc(ev[1]);
    out[4*g+2] = softplus_acc(ev[2]) + 1.0f;
    out[4*g+3] = softplus_acc(ev[3]);
}

extern "C" void kernel_launch(void* const* d_in, const int* in_sizes, int n_in,
                              void* d_out, int out_size) {
    const float* coords = (const float*)d_in[0];
    const float* el     = (const float*)d_in[1];
    const float* evv    = (const float*)d_in[2];
    const float* Wm     = (const float*)d_in[3];
    const float* bm     = (const float*)d_in[4];
    const float* Wo     = (const float*)d_in[5];
    const float* bo     = (const float*)d_in[6];
    const int*   nf     = (const int*)d_in[7];
    const int*   nt     = (const int*)d_in[8];
    const int*   ngi    = (const int*)d_in[9];
    float* out = (float*)d_out;

    float *S0, *S1;
    cudaGetSymbolAddress((void**)&S0, g_S0);
    cudaGetSymbolAddress((void**)&S1, g_S1);

    const int TB = 256;
    int grid_init = (NN * ROW + TB - 1) / TB;
    int grid_copy = (NN * 4 + TB - 1) / TB;
    int grid_edge = (EE + TB - 1) / TB;
    int grid_node = (NN + TB - 1) / TB;
    int grid_out  = (GG + TB - 1) / TB;

    // build: hist -> scan -> to-sorted records (geo computed here)
    init_kernel<<<grid_init, TB>>>(coords);
    hist_kernel<<<grid_edge, TB>>>(nt);
    scan1_kernel<<<NB1, SBS>>>();
    scan2_kernel<<<1, SBS>>>();
    scan3_kernel<<<NB1, SBS>>>();
    scatter_kernel<<<grid_edge, TB>>>(nf, nt, el, evv);

    // round 0: state = 0, accumulate into S1
    round0_kernel<<<grid_edge, TB>>>(Wm, bm, S1);
    // round 1: read S1, accumulate into S0 := S1
    copy_kernel<<<grid_copy, TB>>>((const float4*)S1, (float4*)S0);
    round_kernel<<<grid_edge, TB>>>(Wm, bm, S1, S0);
    // round 2: read S0, accumulate into S1 := S0
    copy_kernel<<<grid_copy, TB>>>((const float4*)S0, (float4*)S1);
    round_kernel<<<grid_edge, TB>>>(Wm, bm, S0, S1);
    // graph reduce + output head
    node_kernel<<<grid_node, TB>>>(ngi, S1);
    out_kernel<<<grid_out, TB>>>(Wo, bo, out);
}